// round 5
// baseline (speedup 1.0000x reference)
#include <cuda_runtime.h>
#include <cuda_bf16.h>
#include <cstdint>
#include <math.h>

// Problem constants
static constexpr int Bn  = 512;    // batch
static constexpr int Nn  = 8192;   // pool
static constexpr int Dn  = 1024;   // pool dim
static constexpr int DAn = 512;    // z dim
static constexpr int Sn  = 8;      // aspects
static constexpr int DKn = 64;     // head dim
static constexpr int Jn  = Sn * DKn; // 512 flattened key/query dim

// ---------------------------------------------------------------------------
// Scratch (device globals; no allocation allowed)
// ---------------------------------------------------------------------------
__device__ __nv_bfloat16 g_Ah[Nn * Dn];   // pool hi   [8192,1024]
__device__ __nv_bfloat16 g_Al[Nn * Dn];   // pool lo
__device__ __nv_bfloat16 g_BhT[Jn * Dn];  // W_K^T hi  [512,1024] (j=a*64+q, p)
__device__ __nv_bfloat16 g_BlT[Jn * Dn];  // W_K^T lo
__device__ __nv_bfloat16 g_Qh[Bn * Jn];   // weighted normalized queries hi [512,512]
__device__ __nv_bfloat16 g_Ql[Bn * Jn];
__device__ __nv_bfloat16 g_Kh[Nn * Jn];   // normalized keys hi [8192,512]
__device__ __nv_bfloat16 g_Kl[Nn * Jn];

// ---------------------------------------------------------------------------
// helpers
// ---------------------------------------------------------------------------
__device__ __forceinline__ uint32_t smem_to_u32(const void* smem_ptr) {
    uint32_t addr;
    asm("{ .reg .u64 tmp; cvta.to.shared.u64 tmp, %1; cvt.u32.u64 %0, tmp; }"
        : "=r"(addr) : "l"(smem_ptr));
    return addr;
}

__device__ __forceinline__ void cp16(uint32_t dst, const void* src) {
    asm volatile("cp.async.cg.shared.global [%0], [%1], 16;"
                 :: "r"(dst), "l"(src) : "memory");
}
#define CP_COMMIT() asm volatile("cp.async.commit_group;" ::: "memory")
#define CP_WAIT(n)  asm volatile("cp.async.wait_group %0;" :: "n"(n) : "memory")

__device__ __forceinline__ void ldsm_x4(uint32_t* r, uint32_t addr) {
    asm volatile("ldmatrix.sync.aligned.m8n8.x4.shared.b16 {%0,%1,%2,%3}, [%4];"
                 : "=r"(r[0]), "=r"(r[1]), "=r"(r[2]), "=r"(r[3]) : "r"(addr));
}

__device__ __forceinline__ void mma_bf16(float* c, const uint32_t* a, const uint32_t* b) {
    asm volatile(
        "mma.sync.aligned.m16n8k16.row.col.f32.bf16.bf16.f32 "
        "{%0,%1,%2,%3}, {%4,%5,%6,%7}, {%8,%9}, {%0,%1,%2,%3};"
        : "+f"(c[0]), "+f"(c[1]), "+f"(c[2]), "+f"(c[3])
        : "r"(a[0]), "r"(a[1]), "r"(a[2]), "r"(a[3]), "r"(b[0]), "r"(b[1]));
}

#define SWZ(off) ((off) ^ (((off) >> 3) & 0x70))

__device__ __forceinline__ void bf16_split(float v, __nv_bfloat16& h, __nv_bfloat16& l) {
    h = __float2bfloat16(v);
    l = __float2bfloat16(v - __bfloat162float(h));
}

// ---------------------------------------------------------------------------
// K0a: split pool fp32 -> bf16 hi/lo. float4 per thread.
// ---------------------------------------------------------------------------
__global__ void __launch_bounds__(256) k_split_pool(const float* __restrict__ X)
{
    int i = blockIdx.x * 256 + threadIdx.x;  // float4 index
    float4 v = ((const float4*)X)[i];
    __nv_bfloat16 h0, h1, h2, h3, l0, l1, l2, l3;
    bf16_split(v.x, h0, l0); bf16_split(v.y, h1, l1);
    bf16_split(v.z, h2, l2); bf16_split(v.w, h3, l3);
    __nv_bfloat162* H2 = (__nv_bfloat162*)g_Ah;
    __nv_bfloat162* L2 = (__nv_bfloat162*)g_Al;
    __nv_bfloat162 a; a.x = h0; a.y = h1;
    __nv_bfloat162 b; b.x = h2; b.y = h3;
    __nv_bfloat162 c; c.x = l0; c.y = l1;
    __nv_bfloat162 d; d.x = l2; d.y = l3;
    H2[2 * i] = a; H2[2 * i + 1] = b;
    L2[2 * i] = c; L2[2 * i + 1] = d;
}

// ---------------------------------------------------------------------------
// K0b: W_K[a,p,q] -> transposed split BhT/BlT[j=a*64+q, p].
// ---------------------------------------------------------------------------
__global__ void __launch_bounds__(256) k_split_wkT(const float* __restrict__ WK)
{
    int idx = blockIdx.x * 256 + threadIdx.x;   // over 512*1024
    int j = idx >> 10, p = idx & 1023;
    int a = j >> 6, q = j & 63;
    float v = WK[a * (Dn * DKn) + p * DKn + q];
    __nv_bfloat16 h, l;
    bf16_split(v, h, l);
    g_BhT[idx] = h;
    g_BlT[idx] = l;
}

// ---------------------------------------------------------------------------
// K1: queries = z @ W_Q, L2-normalize over DK, fold softmax(w), split bf16.
// ---------------------------------------------------------------------------
__global__ void __launch_bounds__(256) k_queries(
    const float* __restrict__ z, const float* __restrict__ WQ,
    const float* __restrict__ logits)
{
    __shared__ float zsh[8][DAn];
    __shared__ float qsh[8][Jn];
    __shared__ float nsh[64];
    __shared__ float wsh[8];

    int t  = threadIdx.x;
    int b0 = blockIdx.x * 8;

    for (int i = t; i < 8 * DAn; i += 256)
        zsh[i >> 9][i & 511] = z[(b0 + (i >> 9)) * DAn + (i & 511)];

    if (t == 0) {
        float m = logits[0];
        for (int i = 1; i < Sn; i++) m = fmaxf(m, logits[i]);
        float ssum = 0.f;
        for (int i = 0; i < Sn; i++) { float e = expf(logits[i] - m); wsh[i] = e; ssum += e; }
        for (int i = 0; i < Sn; i++) wsh[i] /= ssum;
    }
    __syncthreads();

    int c0 = t, c1 = t + 256;
    int a0 = c0 >> 6;
    int a1 = c1 >> 6;
    const float* wq0 = WQ + a0 * DAn * DKn + (c0 & 63);
    const float* wq1 = WQ + a1 * DAn * DKn + (c1 & 63);

    float acc0[8], acc1[8];
#pragma unroll
    for (int bb = 0; bb < 8; bb++) { acc0[bb] = 0.f; acc1[bb] = 0.f; }

    for (int p = 0; p < DAn; p++) {
        float w0 = wq0[p * DKn];
        float w1 = wq1[p * DKn];
#pragma unroll
        for (int bb = 0; bb < 8; bb++) {
            float zv = zsh[bb][p];
            acc0[bb] = fmaf(zv, w0, acc0[bb]);
            acc1[bb] = fmaf(zv, w1, acc1[bb]);
        }
    }
#pragma unroll
    for (int bb = 0; bb < 8; bb++) { qsh[bb][c0] = acc0[bb]; qsh[bb][c1] = acc1[bb]; }
    __syncthreads();

    if (t < 64) {
        int bb = t >> 3, a = t & 7;
        float ss = 0.f;
        for (int q = 0; q < DKn; q++) { float v = qsh[bb][a * DKn + q]; ss = fmaf(v, v, ss); }
        nsh[t] = sqrtf(ss);
    }
    __syncthreads();

#pragma unroll
    for (int bb = 0; bb < 8; bb++) {
        float v0 = wsh[a0] * qsh[bb][c0] / (nsh[bb * 8 + a0] + 1e-8f);
        float v1 = wsh[a1] * qsh[bb][c1] / (nsh[bb * 8 + a1] + 1e-8f);
        __nv_bfloat16 h, l;
        bf16_split(v0, h, l);
        g_Qh[(b0 + bb) * Jn + c0] = h;
        g_Ql[(b0 + bb) * Jn + c0] = l;
        bf16_split(v1, h, l);
        g_Qh[(b0 + bb) * Jn + c1] = h;
        g_Ql[(b0 + bb) * Jn + c1] = l;
    }
}

// ---------------------------------------------------------------------------
// Split-3 bf16 GEMM on mma.sync (HMMA):
//   C[M,N] = Ah*Bh^T + Al*Bh^T + Ah*Bl^T   (fused per k-step)
// 128x128 block tile, BK=64, 256 threads (8 warps, 4m x 2n), warp tile 32x64.
// 3-stage cp.async pipeline, SW128-swizzled smem, ldmatrix fragments.
// Dynamic smem: 3 stages * 4 tiles * 16KB = 192KB.
// FUSE_NORM: epilogue additionally L2-normalizes each output row's 64-wide
// aspect block (fully contained in one warpN block), writes the raw fp32 C
// AND the normalized bf16 hi/lo splits to Kh/Kl.
// ---------------------------------------------------------------------------
template <bool FUSE_NORM>
__global__ void __launch_bounds__(256)
k_gemm_bf16x3(
    const __nv_bfloat16* __restrict__ Ah, const __nv_bfloat16* __restrict__ Al,
    const __nv_bfloat16* __restrict__ Bh, const __nv_bfloat16* __restrict__ Bl,
    float* __restrict__ C, int Ktot, int ldC,
    __nv_bfloat16* __restrict__ Kh, __nv_bfloat16* __restrict__ Kl)
{
    extern __shared__ __align__(1024) uint8_t smem[];
    constexpr uint32_t TILE  = 128 * 128;       // 16 KB per operand tile
    constexpr uint32_t STAGE = 4 * TILE;        // 64 KB per stage

    const int t    = threadIdx.x;
    const int lane = t & 31;
    const int wid  = t >> 5;
    const int warpM = wid & 3;                  // 0..3 -> m offset 32*warpM
    const int warpN = wid >> 2;                 // 0..1 -> n offset 64*warpN
    const int m0 = blockIdx.y * 128;
    const int n0 = blockIdx.x * 128;

    const uint32_t smem_u = smem_to_u32(smem);

    // --- stage loader: 16 cp.async of 16B per thread ---
    auto load_stage = [&](int kt, int s) {
        uint32_t base = smem_u + (uint32_t)s * STAGE;
        int koff = kt * 64;
#pragma unroll
        for (int i = 0; i < 4; i++) {
            int c   = t + i * 256;              // 0..1023
            int row = c >> 3, grp = c & 7;
            uint32_t soff = SWZ((uint32_t)(row * 128 + grp * 16));
            size_t aoff = (size_t)(m0 + row) * Ktot + koff + grp * 8;
            size_t boff = (size_t)(n0 + row) * Ktot + koff + grp * 8;
            cp16(base + soff,            Ah + aoff);
            cp16(base + TILE + soff,     Al + aoff);
            cp16(base + 2 * TILE + soff, Bh + boff);
            cp16(base + 3 * TILE + soff, Bl + boff);
        }
    };

    // --- ldmatrix relative coordinates ---
    const int arow  = warpM * 32 + (lane & 15);  // + mi*16
    const int acolg = (lane >> 4) * 16;          // 0 or 16 bytes (k group)
    const int bg    = lane >> 3;                 // 0..3 matrix select
    const int brow  = warpN * 64 + ((bg >= 2) ? 8 : 0) + (lane & 7); // + njp*16
    const int bcol  = (bg & 1) * 16;             // k group bytes

    float acc[2][8][4];
#pragma unroll
    for (int mi = 0; mi < 2; mi++)
#pragma unroll
        for (int nj = 0; nj < 8; nj++)
#pragma unroll
            for (int r = 0; r < 4; r++) acc[mi][nj][r] = 0.f;

    const int KT = Ktot >> 6;

    // 3-stage pipeline prologue: stages 0 and 1 in flight.
    load_stage(0, 0);
    CP_COMMIT();
    if (KT > 1) load_stage(1, 1);
    CP_COMMIT();

    for (int kt = 0; kt < KT; kt++) {
        CP_WAIT(1);                 // oldest group (stage kt) complete
        __syncthreads();            // data visible to all; prev compute done

        if (kt + 2 < KT) load_stage(kt + 2, (kt + 2) % 3);
        CP_COMMIT();                // exactly one commit per iteration

        uint32_t base = smem_u + (uint32_t)(kt % 3) * STAGE;

#pragma unroll
        for (int ks = 0; ks < 4; ks++) {
            uint32_t ah[2][4], al[2][4], bh[4][4], bl[4][4];
#pragma unroll
            for (int mi = 0; mi < 2; mi++) {
                uint32_t off = SWZ((uint32_t)((arow + mi * 16) * 128 + ks * 32 + acolg));
                ldsm_x4(ah[mi], base + off);
                ldsm_x4(al[mi], base + TILE + off);
            }
#pragma unroll
            for (int njp = 0; njp < 4; njp++) {
                uint32_t off = SWZ((uint32_t)((brow + njp * 16) * 128 + ks * 32 + bcol));
                ldsm_x4(bh[njp], base + 2 * TILE + off);
                ldsm_x4(bl[njp], base + 3 * TILE + off);
            }
#pragma unroll
            for (int mi = 0; mi < 2; mi++)
#pragma unroll
                for (int nj = 0; nj < 8; nj++) {
                    const uint32_t* bhf = &bh[nj >> 1][(nj & 1) * 2];
                    const uint32_t* blf = &bl[nj >> 1][(nj & 1) * 2];
                    mma_bf16(acc[mi][nj], ah[mi], bhf);
                    mma_bf16(acc[mi][nj], al[mi], bhf);
                    mma_bf16(acc[mi][nj], ah[mi], blf);
                }
        }
    }

    // --- epilogue ---
#pragma unroll
    for (int mi = 0; mi < 2; mi++) {
        int r0 = m0 + warpM * 32 + mi * 16 + (lane >> 2);
        int r1 = r0 + 8;
        int colb = n0 + warpN * 64 + (lane & 3) * 2;

        float inv0 = 1.f, inv1 = 1.f;
        if (FUSE_NORM) {
            // ssq over this row's 64-wide aspect block (warpN block == aspect)
            float s0 = 0.f, s1 = 0.f;
#pragma unroll
            for (int nj = 0; nj < 8; nj++) {
                s0 = fmaf(acc[mi][nj][0], acc[mi][nj][0], s0);
                s0 = fmaf(acc[mi][nj][1], acc[mi][nj][1], s0);
                s1 = fmaf(acc[mi][nj][2], acc[mi][nj][2], s1);
                s1 = fmaf(acc[mi][nj][3], acc[mi][nj][3], s1);
            }
            s0 += __shfl_xor_sync(0xffffffffu, s0, 1);
            s0 += __shfl_xor_sync(0xffffffffu, s0, 2);
            s1 += __shfl_xor_sync(0xffffffffu, s1, 1);
            s1 += __shfl_xor_sync(0xffffffffu, s1, 2);
            inv0 = 1.f / (sqrtf(s0) + 1e-8f);
            inv1 = 1.f / (sqrtf(s1) + 1e-8f);
        }

#pragma unroll
        for (int nj = 0; nj < 8; nj++) {
            int col = colb + nj * 8;
            *(float2*)&C[(size_t)r0 * ldC + col] = make_float2(acc[mi][nj][0], acc[mi][nj][1]);
            *(float2*)&C[(size_t)r1 * ldC + col] = make_float2(acc[mi][nj][2], acc[mi][nj][3]);
            if (FUSE_NORM) {
                __nv_bfloat16 h0, l0, h1, l1;
                __nv_bfloat162 hh, ll;
                bf16_split(acc[mi][nj][0] * inv0, h0, l0);
                bf16_split(acc[mi][nj][1] * inv0, h1, l1);
                hh.x = h0; hh.y = h1; ll.x = l0; ll.y = l1;
                *(__nv_bfloat162*)&Kh[(size_t)r0 * ldC + col] = hh;
                *(__nv_bfloat162*)&Kl[(size_t)r0 * ldC + col] = ll;
                bf16_split(acc[mi][nj][2] * inv1, h0, l0);
                bf16_split(acc[mi][nj][3] * inv1, h1, l1);
                hh.x = h0; hh.y = h1; ll.x = l0; ll.y = l1;
                *(__nv_bfloat162*)&Kh[(size_t)r1 * ldC + col] = hh;
                *(__nv_bfloat162*)&Kl[(size_t)r1 * ldC + col] = ll;
            }
        }
    }
}

// ---------------------------------------------------------------------------
// K5: gate + temperature-scaled normalize -> alpha. One block per batch row.
// Fast-math exponentials (MUFU-direct): |rel err| ~1e-6, fine vs 1e-3.
// ---------------------------------------------------------------------------
__global__ void __launch_bounds__(256) k_alpha(
    const float* __restrict__ scores, float* __restrict__ alpha,
    const float* __restrict__ ptau, const float* __restrict__ plam,
    const float* __restrict__ ptemp)
{
    __shared__ float raw[Nn];       // 32 KB
    __shared__ float red[8];
    __shared__ float stot;

    int t = threadIdx.x, b = blockIdx.x;
    float tau = *ptau, lam = *plam, invT = 1.f / (*ptemp);

    float s_local = 0.f;
    const float4* src = (const float4*)(scores + (size_t)b * Nn);
    for (int i = t; i < Nn / 4; i += 256) {
        float4 s4 = src[i];
        float r0 = __expf(s4.x * invT) / (1.f + __expf(-lam * (s4.x - tau)));
        float r1 = __expf(s4.y * invT) / (1.f + __expf(-lam * (s4.y - tau)));
        float r2 = __expf(s4.z * invT) / (1.f + __expf(-lam * (s4.z - tau)));
        float r3 = __expf(s4.w * invT) / (1.f + __expf(-lam * (s4.w - tau)));
        *(float4*)&raw[i * 4] = make_float4(r0, r1, r2, r3);
        s_local += (r0 + r1) + (r2 + r3);
    }
#pragma unroll
    for (int off = 16; off > 0; off >>= 1)
        s_local += __shfl_xor_sync(0xffffffffu, s_local, off);
    if ((t & 31) == 0) red[t >> 5] = s_local;
    __syncthreads();
    if (t == 0) {
        float s = 0.f;
        for (int w = 0; w < 8; w++) s += red[w];
        stot = s;
    }
    __syncthreads();

    float inv = 1.f / (stot + 1e-8f);
    float4* dst = (float4*)(alpha + (size_t)b * Nn);
    for (int i = t; i < Nn / 4; i += 256) {
        float4 r = *(const float4*)&raw[i * 4];
        dst[i] = make_float4(r.x * inv, r.y * inv, r.z * inv, r.w * inv);
    }
}

// ---------------------------------------------------------------------------
extern "C" void kernel_launch(void* const* d_in, const int* in_sizes, int n_in,
                              void* d_out, int out_size)
{
    const float* z      = (const float*)d_in[0];
    const float* pool   = (const float*)d_in[1];
    const float* WQ     = (const float*)d_in[2];
    const float* WK     = (const float*)d_in[3];
    const float* logits = (const float*)d_in[4];
    const float* tau    = (const float*)d_in[5];
    const float* lam    = (const float*)d_in[6];
    const float* temp   = (const float*)d_in[7];

    float* alpha  = (float*)d_out;
    float* scores = alpha  + (size_t)Bn * Nn;
    float* keys   = scores + (size_t)Bn * Nn;

    __nv_bfloat16 *Ah, *Al, *BhT, *BlT, *Qh, *Ql, *Kh, *Kl;
    cudaGetSymbolAddress((void**)&Ah,  g_Ah);
    cudaGetSymbolAddress((void**)&Al,  g_Al);
    cudaGetSymbolAddress((void**)&BhT, g_BhT);
    cudaGetSymbolAddress((void**)&BlT, g_BlT);
    cudaGetSymbolAddress((void**)&Qh,  g_Qh);
    cudaGetSymbolAddress((void**)&Ql,  g_Ql);
    cudaGetSymbolAddress((void**)&Kh,  g_Kh);
    cudaGetSymbolAddress((void**)&Kl,  g_Kl);

    // Not a stream op; safe under graph capture; stateless per contract.
    cudaFuncSetAttribute(k_gemm_bf16x3<true>,
                         cudaFuncAttributeMaxDynamicSharedMemorySize, 196608);
    cudaFuncSetAttribute(k_gemm_bf16x3<false>,
                         cudaFuncAttributeMaxDynamicSharedMemorySize, 196608);

    // operand preparation
    k_split_pool<<<(Nn * Dn / 4) / 256, 256>>>(pool);
    k_split_wkT<<<(Jn * Dn) / 256, 256>>>(WK);
    k_queries<<<Bn / 8, 256>>>(z, WQ, logits);

    // keys[8192,512] = pool @ WkT^T, fused: raw fp32 keys + normalized bf16 splits
    k_gemm_bf16x3<true><<<dim3(Jn / 128, Nn / 128), 256, 196608>>>(
        Ah, Al, BhT, BlT, keys, Dn, Jn, Kh, Kl);

    // scores[512,8192] = Qt @ Khat^T
    k_gemm_bf16x3<false><<<dim3(Nn / 128, Bn / 128), 256, 196608>>>(
        Qh, Ql, Kh, Kl, scores, Jn, Nn, nullptr, nullptr);

    k_alpha<<<Bn, 256>>>(scores, alpha, tau, lam, temp);
}

// round 6
// speedup vs baseline: 1.0224x; 1.0224x over previous
#include <cuda_runtime.h>
#include <cuda_bf16.h>
#include <cstdint>
#include <math.h>

// Problem constants
static constexpr int Bn  = 512;    // batch
static constexpr int Nn  = 8192;   // pool
static constexpr int Dn  = 1024;   // pool dim
static constexpr int DAn = 512;    // z dim
static constexpr int Sn  = 8;      // aspects
static constexpr int DKn = 64;     // head dim
static constexpr int Jn  = Sn * DKn; // 512 flattened key/query dim

// ---------------------------------------------------------------------------
// Scratch (device globals; no allocation allowed)
// ---------------------------------------------------------------------------
__device__ __nv_bfloat16 g_Ah[Nn * Dn];   // pool hi   [8192,1024]
__device__ __nv_bfloat16 g_Al[Nn * Dn];   // pool lo
__device__ __nv_bfloat16 g_BhT[Jn * Dn];  // W_K^T hi  [512,1024] (j=a*64+q, p)
__device__ __nv_bfloat16 g_BlT[Jn * Dn];  // W_K^T lo
__device__ __nv_bfloat16 g_Qh[Bn * Jn];   // weighted normalized queries hi [512,512]
__device__ __nv_bfloat16 g_Ql[Bn * Jn];
__device__ __nv_bfloat16 g_Kh[Nn * Jn];   // normalized keys hi [8192,512]
__device__ __nv_bfloat16 g_Kl[Nn * Jn];

// ---------------------------------------------------------------------------
// helpers
// ---------------------------------------------------------------------------
__device__ __forceinline__ uint32_t smem_to_u32(const void* smem_ptr) {
    uint32_t addr;
    asm("{ .reg .u64 tmp; cvta.to.shared.u64 tmp, %1; cvt.u32.u64 %0, tmp; }"
        : "=r"(addr) : "l"(smem_ptr));
    return addr;
}

__device__ __forceinline__ void cp16(uint32_t dst, const void* src) {
    asm volatile("cp.async.cg.shared.global [%0], [%1], 16;"
                 :: "r"(dst), "l"(src) : "memory");
}
#define CP_COMMIT() asm volatile("cp.async.commit_group;" ::: "memory")
#define CP_WAIT(n)  asm volatile("cp.async.wait_group %0;" :: "n"(n) : "memory")

__device__ __forceinline__ void ldsm_x4(uint32_t* r, uint32_t addr) {
    asm volatile("ldmatrix.sync.aligned.m8n8.x4.shared.b16 {%0,%1,%2,%3}, [%4];"
                 : "=r"(r[0]), "=r"(r[1]), "=r"(r[2]), "=r"(r[3]) : "r"(addr));
}

__device__ __forceinline__ void mma_bf16(float* c, const uint32_t* a, const uint32_t* b) {
    asm volatile(
        "mma.sync.aligned.m16n8k16.row.col.f32.bf16.bf16.f32 "
        "{%0,%1,%2,%3}, {%4,%5,%6,%7}, {%8,%9}, {%0,%1,%2,%3};"
        : "+f"(c[0]), "+f"(c[1]), "+f"(c[2]), "+f"(c[3])
        : "r"(a[0]), "r"(a[1]), "r"(a[2]), "r"(a[3]), "r"(b[0]), "r"(b[1]));
}

#define SWZ(off) ((off) ^ (((off) >> 3) & 0x70))

__device__ __forceinline__ void bf16_split(float v, __nv_bfloat16& h, __nv_bfloat16& l) {
    h = __float2bfloat16(v);
    l = __float2bfloat16(v - __bfloat162float(h));
}

// ---------------------------------------------------------------------------
// K0a: split pool fp32 -> bf16 hi/lo. float4 per thread.
// ---------------------------------------------------------------------------
__global__ void __launch_bounds__(256) k_split_pool(const float* __restrict__ X)
{
    int i = blockIdx.x * 256 + threadIdx.x;  // float4 index
    float4 v = ((const float4*)X)[i];
    __nv_bfloat16 h0, h1, h2, h3, l0, l1, l2, l3;
    bf16_split(v.x, h0, l0); bf16_split(v.y, h1, l1);
    bf16_split(v.z, h2, l2); bf16_split(v.w, h3, l3);
    __nv_bfloat162* H2 = (__nv_bfloat162*)g_Ah;
    __nv_bfloat162* L2 = (__nv_bfloat162*)g_Al;
    __nv_bfloat162 a; a.x = h0; a.y = h1;
    __nv_bfloat162 b; b.x = h2; b.y = h3;
    __nv_bfloat162 c; c.x = l0; c.y = l1;
    __nv_bfloat162 d; d.x = l2; d.y = l3;
    H2[2 * i] = a; H2[2 * i + 1] = b;
    L2[2 * i] = c; L2[2 * i + 1] = d;
}

// ---------------------------------------------------------------------------
// K0b: W_K[a,p,q] -> transposed split BhT/BlT[j=a*64+q, p].
// Coalesced both sides via 64x64 smem tile. grid (8 aspects, 16 p-tiles).
// ---------------------------------------------------------------------------
__global__ void __launch_bounds__(256) k_split_wkT(const float* __restrict__ WK)
{
    __shared__ float tile[64][65];
    int a  = blockIdx.x;
    int p0 = blockIdx.y * 64;
    int t  = threadIdx.x;
    int q  = t & 63, rr = t >> 6;        // rr = 0..3

    const float* src = WK + (size_t)a * (Dn * DKn) + (size_t)p0 * DKn;
#pragma unroll
    for (int pi = rr; pi < 64; pi += 4)
        tile[pi][q] = src[pi * DKn + q];
    __syncthreads();

    // write: row j = a*64+qq, cols p0..p0+63; thread t&63 = pi, t>>6 = qq base
    int pi = t & 63, qb = t >> 6;
#pragma unroll
    for (int qq = qb; qq < 64; qq += 4) {
        float v = tile[pi][qq];
        __nv_bfloat16 h, l;
        bf16_split(v, h, l);
        size_t off = (size_t)(a * 64 + qq) * Dn + p0 + pi;
        g_BhT[off] = h;
        g_BlT[off] = l;
    }
}

// ---------------------------------------------------------------------------
// K1: queries = z @ W_Q, L2-normalize over DK, fold softmax(w), split bf16.
// ---------------------------------------------------------------------------
__global__ void __launch_bounds__(256) k_queries(
    const float* __restrict__ z, const float* __restrict__ WQ,
    const float* __restrict__ logits)
{
    __shared__ float zsh[8][DAn];
    __shared__ float qsh[8][Jn];
    __shared__ float nsh[64];
    __shared__ float wsh[8];

    int t  = threadIdx.x;
    int b0 = blockIdx.x * 8;

    for (int i = t; i < 8 * DAn; i += 256)
        zsh[i >> 9][i & 511] = z[(b0 + (i >> 9)) * DAn + (i & 511)];

    if (t == 0) {
        float m = logits[0];
        for (int i = 1; i < Sn; i++) m = fmaxf(m, logits[i]);
        float ssum = 0.f;
        for (int i = 0; i < Sn; i++) { float e = expf(logits[i] - m); wsh[i] = e; ssum += e; }
        for (int i = 0; i < Sn; i++) wsh[i] /= ssum;
    }
    __syncthreads();

    int c0 = t, c1 = t + 256;
    int a0 = c0 >> 6;
    int a1 = c1 >> 6;
    const float* wq0 = WQ + a0 * DAn * DKn + (c0 & 63);
    const float* wq1 = WQ + a1 * DAn * DKn + (c1 & 63);

    float acc0[8], acc1[8];
#pragma unroll
    for (int bb = 0; bb < 8; bb++) { acc0[bb] = 0.f; acc1[bb] = 0.f; }

    for (int p = 0; p < DAn; p++) {
        float w0 = wq0[p * DKn];
        float w1 = wq1[p * DKn];
#pragma unroll
        for (int bb = 0; bb < 8; bb++) {
            float zv = zsh[bb][p];
            acc0[bb] = fmaf(zv, w0, acc0[bb]);
            acc1[bb] = fmaf(zv, w1, acc1[bb]);
        }
    }
#pragma unroll
    for (int bb = 0; bb < 8; bb++) { qsh[bb][c0] = acc0[bb]; qsh[bb][c1] = acc1[bb]; }
    __syncthreads();

    if (t < 64) {
        int bb = t >> 3, a = t & 7;
        float ss = 0.f;
        for (int q = 0; q < DKn; q++) { float v = qsh[bb][a * DKn + q]; ss = fmaf(v, v, ss); }
        nsh[t] = sqrtf(ss);
    }
    __syncthreads();

#pragma unroll
    for (int bb = 0; bb < 8; bb++) {
        float v0 = wsh[a0] * qsh[bb][c0] / (nsh[bb * 8 + a0] + 1e-8f);
        float v1 = wsh[a1] * qsh[bb][c1] / (nsh[bb * 8 + a1] + 1e-8f);
        __nv_bfloat16 h, l;
        bf16_split(v0, h, l);
        g_Qh[(b0 + bb) * Jn + c0] = h;
        g_Ql[(b0 + bb) * Jn + c0] = l;
        bf16_split(v1, h, l);
        g_Qh[(b0 + bb) * Jn + c1] = h;
        g_Ql[(b0 + bb) * Jn + c1] = l;
    }
}

// ---------------------------------------------------------------------------
// Split-3 bf16 GEMM on mma.sync (HMMA):
//   C[M,N] = Ah*Bh^T + Al*Bh^T + Ah*Bl^T
// 128x128 block tile, BK=64, 512 threads (16 warps, 8m x 2n), warp tile 16x64.
// 3-stage cp.async pipeline, SW128-swizzled smem (192KB).
// 4 warps per SMSP for latency hiding (was 2).
// ---------------------------------------------------------------------------
template <bool FUSE_NORM>
__global__ void __launch_bounds__(512)
k_gemm_bf16x3(
    const __nv_bfloat16* __restrict__ Ah, const __nv_bfloat16* __restrict__ Al,
    const __nv_bfloat16* __restrict__ Bh, const __nv_bfloat16* __restrict__ Bl,
    float* __restrict__ C, int Ktot, int ldC,
    __nv_bfloat16* __restrict__ Kh, __nv_bfloat16* __restrict__ Kl)
{
    extern __shared__ __align__(1024) uint8_t smem[];
    constexpr uint32_t TILE  = 128 * 128;       // 16 KB per operand tile
    constexpr uint32_t STAGE = 4 * TILE;        // 64 KB per stage

    const int t    = threadIdx.x;
    const int lane = t & 31;
    const int wid  = t >> 5;
    const int warpM = wid & 7;                  // 0..7 -> m offset 16*warpM
    const int warpN = wid >> 3;                 // 0..1 -> n offset 64*warpN
    const int m0 = blockIdx.y * 128;
    const int n0 = blockIdx.x * 128;

    const uint32_t smem_u = smem_to_u32(smem);

    // --- stage loader: 8 cp.async of 16B per thread (512 threads) ---
    auto load_stage = [&](int kt, int s) {
        uint32_t base = smem_u + (uint32_t)s * STAGE;
        int koff = kt * 64;
#pragma unroll
        for (int i = 0; i < 2; i++) {
            int c   = t + i * 512;              // 0..1023
            int row = c >> 3, grp = c & 7;
            uint32_t soff = SWZ((uint32_t)(row * 128 + grp * 16));
            size_t aoff = (size_t)(m0 + row) * Ktot + koff + grp * 8;
            size_t boff = (size_t)(n0 + row) * Ktot + koff + grp * 8;
            cp16(base + soff,            Ah + aoff);
            cp16(base + TILE + soff,     Al + aoff);
            cp16(base + 2 * TILE + soff, Bh + boff);
            cp16(base + 3 * TILE + soff, Bl + boff);
        }
    };

    // --- ldmatrix relative coordinates ---
    const int arow  = warpM * 16 + (lane & 15);
    const int acolg = (lane >> 4) * 16;          // 0 or 16 bytes (k group)
    const int bg    = lane >> 3;                 // 0..3 matrix select
    const int brow  = warpN * 64 + ((bg >= 2) ? 8 : 0) + (lane & 7); // + njp*16
    const int bcol  = (bg & 1) * 16;             // k group bytes

    float acc[8][4];
#pragma unroll
    for (int nj = 0; nj < 8; nj++)
#pragma unroll
        for (int r = 0; r < 4; r++) acc[nj][r] = 0.f;

    const int KT = Ktot >> 6;

    // 3-stage pipeline prologue: stages 0 and 1 in flight.
    load_stage(0, 0);
    CP_COMMIT();
    if (KT > 1) load_stage(1, 1);
    CP_COMMIT();

    for (int kt = 0; kt < KT; kt++) {
        CP_WAIT(1);                 // oldest group (stage kt) complete
        __syncthreads();            // data visible; prev compute done

        if (kt + 2 < KT) load_stage(kt + 2, (kt + 2) % 3);
        CP_COMMIT();                // one commit per iteration

        uint32_t base = smem_u + (uint32_t)(kt % 3) * STAGE;

#pragma unroll
        for (int ks = 0; ks < 4; ks++) {
            uint32_t ah[4], al[4], bh[4][4], bl[4][4];
            {
                uint32_t off = SWZ((uint32_t)(arow * 128 + ks * 32 + acolg));
                ldsm_x4(ah, base + off);
                ldsm_x4(al, base + TILE + off);
            }
#pragma unroll
            for (int njp = 0; njp < 4; njp++) {
                uint32_t off = SWZ((uint32_t)((brow + njp * 16) * 128 + ks * 32 + bcol));
                ldsm_x4(bh[njp], base + 2 * TILE + off);
                ldsm_x4(bl[njp], base + 3 * TILE + off);
            }
#pragma unroll
            for (int nj = 0; nj < 8; nj++) {
                const uint32_t* bhf = &bh[nj >> 1][(nj & 1) * 2];
                const uint32_t* blf = &bl[nj >> 1][(nj & 1) * 2];
                mma_bf16(acc[nj], ah, bhf);
                mma_bf16(acc[nj], al, bhf);
                mma_bf16(acc[nj], ah, blf);
            }
        }
    }

    // --- epilogue ---
    {
        int r0 = m0 + warpM * 16 + (lane >> 2);
        int r1 = r0 + 8;
        int colb = n0 + warpN * 64 + (lane & 3) * 2;

        float inv0 = 1.f, inv1 = 1.f;
        if (FUSE_NORM) {
            // ssq over this row's 64-wide aspect block (warpN block == aspect)
            float s0 = 0.f, s1 = 0.f;
#pragma unroll
            for (int nj = 0; nj < 8; nj++) {
                s0 = fmaf(acc[nj][0], acc[nj][0], s0);
                s0 = fmaf(acc[nj][1], acc[nj][1], s0);
                s1 = fmaf(acc[nj][2], acc[nj][2], s1);
                s1 = fmaf(acc[nj][3], acc[nj][3], s1);
            }
            s0 += __shfl_xor_sync(0xffffffffu, s0, 1);
            s0 += __shfl_xor_sync(0xffffffffu, s0, 2);
            s1 += __shfl_xor_sync(0xffffffffu, s1, 1);
            s1 += __shfl_xor_sync(0xffffffffu, s1, 2);
            inv0 = 1.f / (sqrtf(s0) + 1e-8f);
            inv1 = 1.f / (sqrtf(s1) + 1e-8f);
        }

#pragma unroll
        for (int nj = 0; nj < 8; nj++) {
            int col = colb + nj * 8;
            *(float2*)&C[(size_t)r0 * ldC + col] = make_float2(acc[nj][0], acc[nj][1]);
            *(float2*)&C[(size_t)r1 * ldC + col] = make_float2(acc[nj][2], acc[nj][3]);
            if (FUSE_NORM) {
                __nv_bfloat16 h0, l0, h1, l1;
                __nv_bfloat162 hh, ll;
                bf16_split(acc[nj][0] * inv0, h0, l0);
                bf16_split(acc[nj][1] * inv0, h1, l1);
                hh.x = h0; hh.y = h1; ll.x = l0; ll.y = l1;
                *(__nv_bfloat162*)&Kh[(size_t)r0 * ldC + col] = hh;
                *(__nv_bfloat162*)&Kl[(size_t)r0 * ldC + col] = ll;
                bf16_split(acc[nj][2] * inv1, h0, l0);
                bf16_split(acc[nj][3] * inv1, h1, l1);
                hh.x = h0; hh.y = h1; ll.x = l0; ll.y = l1;
                *(__nv_bfloat162*)&Kh[(size_t)r1 * ldC + col] = hh;
                *(__nv_bfloat162*)&Kl[(size_t)r1 * ldC + col] = ll;
            }
        }
    }
}

// ---------------------------------------------------------------------------
// K5: gate + temperature-scaled normalize -> alpha. One block per batch row.
// ---------------------------------------------------------------------------
__global__ void __launch_bounds__(256) k_alpha(
    const float* __restrict__ scores, float* __restrict__ alpha,
    const float* __restrict__ ptau, const float* __restrict__ plam,
    const float* __restrict__ ptemp)
{
    __shared__ float raw[Nn];       // 32 KB
    __shared__ float red[8];
    __shared__ float stot;

    int t = threadIdx.x, b = blockIdx.x;
    float tau = *ptau, lam = *plam, invT = 1.f / (*ptemp);

    float s_local = 0.f;
    const float4* src = (const float4*)(scores + (size_t)b * Nn);
    for (int i = t; i < Nn / 4; i += 256) {
        float4 s4 = src[i];
        float r0 = __expf(s4.x * invT) / (1.f + __expf(-lam * (s4.x - tau)));
        float r1 = __expf(s4.y * invT) / (1.f + __expf(-lam * (s4.y - tau)));
        float r2 = __expf(s4.z * invT) / (1.f + __expf(-lam * (s4.z - tau)));
        float r3 = __expf(s4.w * invT) / (1.f + __expf(-lam * (s4.w - tau)));
        *(float4*)&raw[i * 4] = make_float4(r0, r1, r2, r3);
        s_local += (r0 + r1) + (r2 + r3);
    }
#pragma unroll
    for (int off = 16; off > 0; off >>= 1)
        s_local += __shfl_xor_sync(0xffffffffu, s_local, off);
    if ((t & 31) == 0) red[t >> 5] = s_local;
    __syncthreads();
    if (t == 0) {
        float s = 0.f;
        for (int w = 0; w < 8; w++) s += red[w];
        stot = s;
    }
    __syncthreads();

    float inv = 1.f / (stot + 1e-8f);
    float4* dst = (float4*)(alpha + (size_t)b * Nn);
    for (int i = t; i < Nn / 4; i += 256) {
        float4 r = *(const float4*)&raw[i * 4];
        dst[i] = make_float4(r.x * inv, r.y * inv, r.z * inv, r.w * inv);
    }
}

// ---------------------------------------------------------------------------
extern "C" void kernel_launch(void* const* d_in, const int* in_sizes, int n_in,
                              void* d_out, int out_size)
{
    const float* z      = (const float*)d_in[0];
    const float* pool   = (const float*)d_in[1];
    const float* WQ     = (const float*)d_in[2];
    const float* WK     = (const float*)d_in[3];
    const float* logits = (const float*)d_in[4];
    const float* tau    = (const float*)d_in[5];
    const float* lam    = (const float*)d_in[6];
    const float* temp   = (const float*)d_in[7];

    float* alpha  = (float*)d_out;
    float* scores = alpha  + (size_t)Bn * Nn;
    float* keys   = scores + (size_t)Bn * Nn;

    __nv_bfloat16 *Ah, *Al, *BhT, *BlT, *Qh, *Ql, *Kh, *Kl;
    cudaGetSymbolAddress((void**)&Ah,  g_Ah);
    cudaGetSymbolAddress((void**)&Al,  g_Al);
    cudaGetSymbolAddress((void**)&BhT, g_BhT);
    cudaGetSymbolAddress((void**)&BlT, g_BlT);
    cudaGetSymbolAddress((void**)&Qh,  g_Qh);
    cudaGetSymbolAddress((void**)&Ql,  g_Ql);
    cudaGetSymbolAddress((void**)&Kh,  g_Kh);
    cudaGetSymbolAddress((void**)&Kl,  g_Kl);

    // Not a stream op; safe under graph capture; stateless per contract.
    cudaFuncSetAttribute(k_gemm_bf16x3<true>,
                         cudaFuncAttributeMaxDynamicSharedMemorySize, 196608);
    cudaFuncSetAttribute(k_gemm_bf16x3<false>,
                         cudaFuncAttributeMaxDynamicSharedMemorySize, 196608);

    // operand preparation
    k_split_pool<<<(Nn * Dn / 4) / 256, 256>>>(pool);
    k_split_wkT<<<dim3(Sn, Dn / 64), 256>>>(WK);
    k_queries<<<Bn / 8, 256>>>(z, WQ, logits);

    // keys[8192,512] = pool @ WkT^T, fused: raw fp32 keys + normalized bf16 splits
    k_gemm_bf16x3<true><<<dim3(Jn / 128, Nn / 128), 512, 196608>>>(
        Ah, Al, BhT, BlT, keys, Dn, Jn, Kh, Kl);

    // scores[512,8192] = Qt @ Khat^T
    k_gemm_bf16x3<false><<<dim3(Nn / 128, Bn / 128), 512, 196608>>>(
        Qh, Ql, Kh, Kl, scores, Jn, Nn, nullptr, nullptr);

    k_alpha<<<Bn, 256>>>(scores, alpha, tau, lam, temp);
}

// round 7
// speedup vs baseline: 1.5287x; 1.4952x over previous
#include <cuda_runtime.h>
#include <cuda_bf16.h>
#include <cstdint>
#include <math.h>

// Problem constants
static constexpr int Bn  = 512;    // batch
static constexpr int Nn  = 8192;   // pool
static constexpr int Dn  = 1024;   // pool dim
static constexpr int DAn = 512;    // z dim
static constexpr int Sn  = 8;      // aspects
static constexpr int DKn = 64;     // head dim
static constexpr int Jn  = Sn * DKn; // 512 flattened key/query dim

// ---------------------------------------------------------------------------
// Scratch (device globals; no allocation allowed)
// ---------------------------------------------------------------------------
__device__ __nv_bfloat16 g_Ah[Nn * Dn];    // pool hi   [8192,1024]
__device__ __nv_bfloat16 g_Al[Nn * Dn];    // pool lo
__device__ __nv_bfloat16 g_BhT[Jn * Dn];   // W_K^T hi  [512,1024]
__device__ __nv_bfloat16 g_BlT[Jn * Dn];   // W_K^T lo
__device__ __nv_bfloat16 g_Zh[Bn * DAn];   // z hi      [512,512]
__device__ __nv_bfloat16 g_Zl[Bn * DAn];
__device__ __nv_bfloat16 g_WQh[Jn * DAn];  // W_Q^T hi  [512,512]
__device__ __nv_bfloat16 g_WQl[Jn * DAn];
__device__ __nv_bfloat16 g_Qh[Bn * Jn];    // weighted normalized queries hi
__device__ __nv_bfloat16 g_Ql[Bn * Jn];
__device__ __nv_bfloat16 g_Kh[Nn * Jn];    // normalized keys hi [8192,512]
__device__ __nv_bfloat16 g_Kl[Nn * Jn];
__device__ float         g_qraw[Bn * Jn];  // raw queries fp32 (discarded)
__device__ float         g_w[Sn];          // softmax(aspect_logits)

// ---------------------------------------------------------------------------
// helpers
// ---------------------------------------------------------------------------
__device__ __forceinline__ uint32_t smem_to_u32(const void* smem_ptr) {
    uint32_t addr;
    asm("{ .reg .u64 tmp; cvta.to.shared.u64 tmp, %1; cvt.u32.u64 %0, tmp; }"
        : "=r"(addr) : "l"(smem_ptr));
    return addr;
}

__device__ __forceinline__ void cp16(uint32_t dst, const void* src) {
    asm volatile("cp.async.cg.shared.global [%0], [%1], 16;"
                 :: "r"(dst), "l"(src) : "memory");
}
#define CP_COMMIT() asm volatile("cp.async.commit_group;" ::: "memory")
#define CP_WAIT(n)  asm volatile("cp.async.wait_group %0;" :: "n"(n) : "memory")

__device__ __forceinline__ void ldsm_x4(uint32_t* r, uint32_t addr) {
    asm volatile("ldmatrix.sync.aligned.m8n8.x4.shared.b16 {%0,%1,%2,%3}, [%4];"
                 : "=r"(r[0]), "=r"(r[1]), "=r"(r[2]), "=r"(r[3]) : "r"(addr));
}

__device__ __forceinline__ void mma_bf16(float* c, const uint32_t* a, const uint32_t* b) {
    asm volatile(
        "mma.sync.aligned.m16n8k16.row.col.f32.bf16.bf16.f32 "
        "{%0,%1,%2,%3}, {%4,%5,%6,%7}, {%8,%9}, {%0,%1,%2,%3};"
        : "+f"(c[0]), "+f"(c[1]), "+f"(c[2]), "+f"(c[3])
        : "r"(a[0]), "r"(a[1]), "r"(a[2]), "r"(a[3]), "r"(b[0]), "r"(b[1]));
}

#define SWZ(off) ((off) ^ (((off) >> 3) & 0x70))

__device__ __forceinline__ void bf16_split(float v, __nv_bfloat16& h, __nv_bfloat16& l) {
    h = __float2bfloat16(v);
    l = __float2bfloat16(v - __bfloat162float(h));
}

// ---------------------------------------------------------------------------
// K0: generic fp32 -> bf16 hi/lo split. float4 per thread.
// ---------------------------------------------------------------------------
__global__ void __launch_bounds__(256) k_split(
    const float* __restrict__ X, __nv_bfloat16* __restrict__ H,
    __nv_bfloat16* __restrict__ L)
{
    int i = blockIdx.x * 256 + threadIdx.x;  // float4 index
    float4 v = ((const float4*)X)[i];
    __nv_bfloat16 h0, h1, h2, h3, l0, l1, l2, l3;
    bf16_split(v.x, h0, l0); bf16_split(v.y, h1, l1);
    bf16_split(v.z, h2, l2); bf16_split(v.w, h3, l3);
    __nv_bfloat162 a; a.x = h0; a.y = h1;
    __nv_bfloat162 b; b.x = h2; b.y = h3;
    __nv_bfloat162 c; c.x = l0; c.y = l1;
    __nv_bfloat162 d; d.x = l2; d.y = l3;
    ((__nv_bfloat162*)H)[2 * i] = a; ((__nv_bfloat162*)H)[2 * i + 1] = b;
    ((__nv_bfloat162*)L)[2 * i] = c; ((__nv_bfloat162*)L)[2 * i + 1] = d;
}

// ---------------------------------------------------------------------------
// K0T: W[a,p,q] (p<D, q<64) -> transposed split dst[(a*64+q), p] hi/lo.
// grid (Sn, D/64), block 256, 64x64 smem tile.
// ---------------------------------------------------------------------------
__global__ void __launch_bounds__(256) k_split_T(
    const float* __restrict__ W, __nv_bfloat16* __restrict__ H,
    __nv_bfloat16* __restrict__ L, int D)
{
    __shared__ float tile[64][65];
    int a  = blockIdx.x;
    int p0 = blockIdx.y * 64;
    int t  = threadIdx.x;
    int q  = t & 63, rr = t >> 6;

    const float* src = W + (size_t)a * (D * DKn) + (size_t)p0 * DKn;
#pragma unroll
    for (int pi = rr; pi < 64; pi += 4)
        tile[pi][q] = src[pi * DKn + q];
    __syncthreads();

    int pi = t & 63, qb = t >> 6;
#pragma unroll
    for (int qq = qb; qq < 64; qq += 4) {
        float v = tile[pi][qq];
        __nv_bfloat16 h, l;
        bf16_split(v, h, l);
        size_t off = (size_t)(a * 64 + qq) * D + p0 + pi;
        H[off] = h;
        L[off] = l;
    }
}

// ---------------------------------------------------------------------------
// softmax of aspect logits -> g_w
// ---------------------------------------------------------------------------
__global__ void k_softmax_w(const float* __restrict__ logits)
{
    if (threadIdx.x == 0) {
        float m = logits[0];
        for (int i = 1; i < Sn; i++) m = fmaxf(m, logits[i]);
        float e[Sn], s = 0.f;
        for (int i = 0; i < Sn; i++) { e[i] = expf(logits[i] - m); s += e[i]; }
        for (int i = 0; i < Sn; i++) g_w[i] = e[i] / s;
    }
}

// ---------------------------------------------------------------------------
// Split-3 bf16 GEMM on mma.sync:
//   C[M,N] = Ah*Bh^T + Al*Bh^T + Ah*Bl^T
// 128(M) x 256(N) block tile, BK=64, 512 threads (16 warps, 4m x 4n),
// warp tile 32x64. 2-stage cp.async double buffer, SW128 swizzle.
// Stage: Ah 16K | Al 16K | Bh 32K | Bl 32K = 96KB; 2 stages = 192KB.
// FUSE_NORM: L2-normalize each row's 64-wide aspect block (== warpN block),
// optionally scale by Wv[aspect], write bf16 hi/lo splits to Kh/Kl.
// grid: (N/256, M/128)
// ---------------------------------------------------------------------------
template <bool FUSE_NORM>
__global__ void __launch_bounds__(512)
k_gemm_bf16x3(
    const __nv_bfloat16* __restrict__ Ah, const __nv_bfloat16* __restrict__ Al,
    const __nv_bfloat16* __restrict__ Bh, const __nv_bfloat16* __restrict__ Bl,
    float* __restrict__ C, int Ktot, int ldC,
    __nv_bfloat16* __restrict__ Kh, __nv_bfloat16* __restrict__ Kl,
    const float* __restrict__ Wv)
{
    extern __shared__ __align__(1024) uint8_t smem[];
    constexpr uint32_t AT    = 128 * 128;       // 16 KB A tile (h or l)
    constexpr uint32_t BT    = 256 * 128;       // 32 KB B tile (h or l)
    constexpr uint32_t OFF_AL = AT;             // 16K
    constexpr uint32_t OFF_BH = 2 * AT;         // 32K
    constexpr uint32_t OFF_BL = 2 * AT + BT;    // 64K
    constexpr uint32_t STAGE  = 2 * AT + 2 * BT; // 96 KB

    const int t    = threadIdx.x;
    const int lane = t & 31;
    const int wid  = t >> 5;
    const int warpM = wid & 3;                  // m offset 32*warpM
    const int warpN = wid >> 2;                 // n offset 64*warpN
    const int m0 = blockIdx.y * 128;
    const int n0 = blockIdx.x * 256;

    const uint32_t smem_u = smem_to_u32(smem);

    // --- stage loader: 12 cp.async of 16B per thread ---
    auto load_stage = [&](int kt, int s) {
        uint32_t base = smem_u + (uint32_t)s * STAGE;
        int koff = kt * 64;
#pragma unroll
        for (int i = 0; i < 2; i++) {           // A: 1024 chunks
            int c   = t + i * 512;
            int row = c >> 3, grp = c & 7;
            uint32_t soff = SWZ((uint32_t)(row * 128 + grp * 16));
            size_t aoff = (size_t)(m0 + row) * Ktot + koff + grp * 8;
            cp16(base + soff,          Ah + aoff);
            cp16(base + OFF_AL + soff, Al + aoff);
        }
#pragma unroll
        for (int i = 0; i < 4; i++) {           // B: 2048 chunks
            int c   = t + i * 512;
            int row = c >> 3, grp = c & 7;
            uint32_t soff = SWZ((uint32_t)(row * 128 + grp * 16));
            size_t boff = (size_t)(n0 + row) * Ktot + koff + grp * 8;
            cp16(base + OFF_BH + soff, Bh + boff);
            cp16(base + OFF_BL + soff, Bl + boff);
        }
    };

    // --- ldmatrix relative coordinates ---
    const int arow  = warpM * 32 + (lane & 15);  // + mi*16
    const int acolg = (lane >> 4) * 16;
    const int bg    = lane >> 3;
    const int brow  = warpN * 64 + ((bg >= 2) ? 8 : 0) + (lane & 7); // + njp*16
    const int bcol  = (bg & 1) * 16;

    float acc[2][8][4];
#pragma unroll
    for (int mi = 0; mi < 2; mi++)
#pragma unroll
        for (int nj = 0; nj < 8; nj++)
#pragma unroll
            for (int r = 0; r < 4; r++) acc[mi][nj][r] = 0.f;

    const int KT = Ktot >> 6;

    load_stage(0, 0);
    CP_COMMIT();

    for (int kt = 0; kt < KT; kt++) {
        if (kt + 1 < KT) {
            load_stage(kt + 1, (kt + 1) & 1);
            CP_COMMIT();
            CP_WAIT(1);
        } else {
            CP_WAIT(0);
        }
        __syncthreads();

        uint32_t base = smem_u + (uint32_t)(kt & 1) * STAGE;

#pragma unroll
        for (int ks = 0; ks < 4; ks++) {
            uint32_t ah[2][4], al[2][4];
#pragma unroll
            for (int mi = 0; mi < 2; mi++) {
                uint32_t off = SWZ((uint32_t)((arow + mi * 16) * 128 + ks * 32 + acolg));
                ldsm_x4(ah[mi], base + off);
                ldsm_x4(al[mi], base + OFF_AL + off);
            }
#pragma unroll
            for (int njp = 0; njp < 4; njp++) {
                uint32_t bh[4], bl[4];
                uint32_t off = SWZ((uint32_t)((brow + njp * 16) * 128 + ks * 32 + bcol));
                ldsm_x4(bh, base + OFF_BH + off);
                ldsm_x4(bl, base + OFF_BL + off);
#pragma unroll
                for (int half = 0; half < 2; half++) {
                    int nj = njp * 2 + half;
                    const uint32_t* bhf = &bh[half * 2];
                    const uint32_t* blf = &bl[half * 2];
#pragma unroll
                    for (int mi = 0; mi < 2; mi++) {
                        mma_bf16(acc[mi][nj], ah[mi], bhf);
                        mma_bf16(acc[mi][nj], al[mi], bhf);
                        mma_bf16(acc[mi][nj], ah[mi], blf);
                    }
                }
            }
        }
        __syncthreads();
    }

    // --- epilogue ---
    float wa = 1.f;
    if (FUSE_NORM && Wv != nullptr) wa = Wv[(n0 + warpN * 64) >> 6];

#pragma unroll
    for (int mi = 0; mi < 2; mi++) {
        int r0 = m0 + warpM * 32 + mi * 16 + (lane >> 2);
        int r1 = r0 + 8;
        int colb = n0 + warpN * 64 + (lane & 3) * 2;

        float inv0 = 1.f, inv1 = 1.f;
        if (FUSE_NORM) {
            float s0 = 0.f, s1 = 0.f;
#pragma unroll
            for (int nj = 0; nj < 8; nj++) {
                s0 = fmaf(acc[mi][nj][0], acc[mi][nj][0], s0);
                s0 = fmaf(acc[mi][nj][1], acc[mi][nj][1], s0);
                s1 = fmaf(acc[mi][nj][2], acc[mi][nj][2], s1);
                s1 = fmaf(acc[mi][nj][3], acc[mi][nj][3], s1);
            }
            s0 += __shfl_xor_sync(0xffffffffu, s0, 1);
            s0 += __shfl_xor_sync(0xffffffffu, s0, 2);
            s1 += __shfl_xor_sync(0xffffffffu, s1, 1);
            s1 += __shfl_xor_sync(0xffffffffu, s1, 2);
            inv0 = wa / (sqrtf(s0) + 1e-8f);
            inv1 = wa / (sqrtf(s1) + 1e-8f);
        }

#pragma unroll
        for (int nj = 0; nj < 8; nj++) {
            int col = colb + nj * 8;
            *(float2*)&C[(size_t)r0 * ldC + col] = make_float2(acc[mi][nj][0], acc[mi][nj][1]);
            *(float2*)&C[(size_t)r1 * ldC + col] = make_float2(acc[mi][nj][2], acc[mi][nj][3]);
            if (FUSE_NORM) {
                __nv_bfloat16 h0, l0, h1, l1;
                __nv_bfloat162 hh, ll;
                bf16_split(acc[mi][nj][0] * inv0, h0, l0);
                bf16_split(acc[mi][nj][1] * inv0, h1, l1);
                hh.x = h0; hh.y = h1; ll.x = l0; ll.y = l1;
                *(__nv_bfloat162*)&Kh[(size_t)r0 * ldC + col] = hh;
                *(__nv_bfloat162*)&Kl[(size_t)r0 * ldC + col] = ll;
                bf16_split(acc[mi][nj][2] * inv1, h0, l0);
                bf16_split(acc[mi][nj][3] * inv1, h1, l1);
                hh.x = h0; hh.y = h1; ll.x = l0; ll.y = l1;
                *(__nv_bfloat162*)&Kh[(size_t)r1 * ldC + col] = hh;
                *(__nv_bfloat162*)&Kl[(size_t)r1 * ldC + col] = ll;
            }
        }
    }
}

// ---------------------------------------------------------------------------
// K5: gate + temperature-scaled normalize -> alpha. One block per batch row.
// ---------------------------------------------------------------------------
__global__ void __launch_bounds__(256) k_alpha(
    const float* __restrict__ scores, float* __restrict__ alpha,
    const float* __restrict__ ptau, const float* __restrict__ plam,
    const float* __restrict__ ptemp)
{
    __shared__ float raw[Nn];       // 32 KB
    __shared__ float red[8];
    __shared__ float stot;

    int t = threadIdx.x, b = blockIdx.x;
    float tau = *ptau, lam = *plam, invT = 1.f / (*ptemp);

    float s_local = 0.f;
    const float4* src = (const float4*)(scores + (size_t)b * Nn);
    for (int i = t; i < Nn / 4; i += 256) {
        float4 s4 = src[i];
        float r0 = __expf(s4.x * invT) / (1.f + __expf(-lam * (s4.x - tau)));
        float r1 = __expf(s4.y * invT) / (1.f + __expf(-lam * (s4.y - tau)));
        float r2 = __expf(s4.z * invT) / (1.f + __expf(-lam * (s4.z - tau)));
        float r3 = __expf(s4.w * invT) / (1.f + __expf(-lam * (s4.w - tau)));
        *(float4*)&raw[i * 4] = make_float4(r0, r1, r2, r3);
        s_local += (r0 + r1) + (r2 + r3);
    }
#pragma unroll
    for (int off = 16; off > 0; off >>= 1)
        s_local += __shfl_xor_sync(0xffffffffu, s_local, off);
    if ((t & 31) == 0) red[t >> 5] = s_local;
    __syncthreads();
    if (t == 0) {
        float s = 0.f;
        for (int w = 0; w < 8; w++) s += red[w];
        stot = s;
    }
    __syncthreads();

    float inv = 1.f / (stot + 1e-8f);
    float4* dst = (float4*)(alpha + (size_t)b * Nn);
    for (int i = t; i < Nn / 4; i += 256) {
        float4 r = *(const float4*)&raw[i * 4];
        dst[i] = make_float4(r.x * inv, r.y * inv, r.z * inv, r.w * inv);
    }
}

// ---------------------------------------------------------------------------
extern "C" void kernel_launch(void* const* d_in, const int* in_sizes, int n_in,
                              void* d_out, int out_size)
{
    const float* z      = (const float*)d_in[0];
    const float* pool   = (const float*)d_in[1];
    const float* WQ     = (const float*)d_in[2];
    const float* WK     = (const float*)d_in[3];
    const float* logits = (const float*)d_in[4];
    const float* tau    = (const float*)d_in[5];
    const float* lam    = (const float*)d_in[6];
    const float* temp   = (const float*)d_in[7];

    float* alpha  = (float*)d_out;
    float* scores = alpha  + (size_t)Bn * Nn;
    float* keys   = scores + (size_t)Bn * Nn;

    __nv_bfloat16 *Ah, *Al, *BhT, *BlT, *Zh, *Zl, *WQh, *WQl, *Qh, *Ql, *Kh, *Kl;
    float *qraw, *wv;
    cudaGetSymbolAddress((void**)&Ah,   g_Ah);
    cudaGetSymbolAddress((void**)&Al,   g_Al);
    cudaGetSymbolAddress((void**)&BhT,  g_BhT);
    cudaGetSymbolAddress((void**)&BlT,  g_BlT);
    cudaGetSymbolAddress((void**)&Zh,   g_Zh);
    cudaGetSymbolAddress((void**)&Zl,   g_Zl);
    cudaGetSymbolAddress((void**)&WQh,  g_WQh);
    cudaGetSymbolAddress((void**)&WQl,  g_WQl);
    cudaGetSymbolAddress((void**)&Qh,   g_Qh);
    cudaGetSymbolAddress((void**)&Ql,   g_Ql);
    cudaGetSymbolAddress((void**)&Kh,   g_Kh);
    cudaGetSymbolAddress((void**)&Kl,   g_Kl);
    cudaGetSymbolAddress((void**)&qraw, g_qraw);
    cudaGetSymbolAddress((void**)&wv,   g_w);

    // Not a stream op; safe under graph capture; stateless per contract.
    cudaFuncSetAttribute(k_gemm_bf16x3<true>,
                         cudaFuncAttributeMaxDynamicSharedMemorySize, 196608);
    cudaFuncSetAttribute(k_gemm_bf16x3<false>,
                         cudaFuncAttributeMaxDynamicSharedMemorySize, 196608);

    // prep
    k_softmax_w<<<1, 32>>>(logits);
    k_split<<<(Bn * DAn / 4) / 256, 256>>>(z, Zh, Zl);
    k_split_T<<<dim3(Sn, DAn / 64), 256>>>(WQ, WQh, WQl, DAn);
    k_split<<<(Nn * Dn / 4) / 256, 256>>>(pool, Ah, Al);
    k_split_T<<<dim3(Sn, Dn / 64), 256>>>(WK, BhT, BlT, Dn);

    // GEMM0: queries[512,512] = z @ WQT^T; fused norm + aspect weight -> Qh/Ql
    k_gemm_bf16x3<true><<<dim3(Jn / 256, Bn / 128), 512, 196608>>>(
        Zh, Zl, WQh, WQl, qraw, DAn, Jn, Qh, Ql, wv);

    // GEMM1: keys[8192,512] = pool @ WkT^T; fused norm -> Kh/Kl (raw fp32 keys out)
    k_gemm_bf16x3<true><<<dim3(Jn / 256, Nn / 128), 512, 196608>>>(
        Ah, Al, BhT, BlT, keys, Dn, Jn, Kh, Kl, nullptr);

    // GEMM2: scores[512,8192] = Qt @ Khat^T
    k_gemm_bf16x3<false><<<dim3(Nn / 256, Bn / 128), 512, 196608>>>(
        Qh, Ql, Kh, Kl, scores, Jn, Nn, nullptr, nullptr, nullptr);

    k_alpha<<<Bn, 256>>>(scores, alpha, tau, lam, temp);
}